// round 11
// baseline (speedup 1.0000x reference)
#include <cuda_runtime.h>
#include <cuda_bf16.h>
#include <cstdint>

#define BATCH 2
#define H 512
#define W 512
#define NWORDS (W / 32)          // 16
#define INF_SQ 1e12f

// Row-pass output, packed: .x = dist^2 to nearest fg (mask==1) in the row,
//                          .y = dist^2 to nearest bg (mask==0) in the row.
__device__ float2 g_row[BATCH * H * W];

// Nearest set bit to position i in a 512-bit mask (16 words). Returns a huge
// value if no bit is set. Typical path: no word-escape loops taken.
__device__ __forceinline__ int nearest_set_bit(const uint32_t* __restrict__ m, int i) {
    const int wi = i >> 5, bi = i & 31;
    int dL = 1 << 20, dR = 1 << 20;

    const uint32_t below = m[wi] & (0xffffffffu >> (31 - bi));   // bits 0..bi
    if (below) {
        dL = bi - (31 - __clz(below));
    } else {
        for (int j = wi - 1; j >= 0; --j)
            if (m[j]) { dL = i - (j * 32 + 31 - __clz(m[j])); break; }
    }

    const uint32_t above = m[wi] & (0xffffffffu << bi);          // bits bi..31
    if (above) {
        dR = (__ffs(above) - 1) - bi;
    } else {
        for (int j = wi + 1; j < NWORDS; ++j)
            if (m[j]) { dR = j * 32 + (__ffs(m[j]) - 1) - i; break; }
    }

    return min(dL, dR);
}

// -------- Row pass: one block per row; ballot bitmask + O(1) bit search. ----
__global__ void __launch_bounds__(W) row_pass(const float* __restrict__ mask) {
    __shared__ uint32_t fgm[NWORDS];
    __shared__ uint32_t bgm[NWORDS];

    const int row = blockIdx.x;          // 0 .. BATCH*H-1
    const int i   = threadIdx.x;

    const bool isFg = (mask[row * W + i] == 1.0f);
    const uint32_t wm = __ballot_sync(0xffffffffu, isFg);
    if ((i & 31) == 0) {
        fgm[i >> 5] = wm;
        bgm[i >> 5] = ~wm;               // W==512 exactly fills 16 words
    }
    __syncthreads();

    const int dfg = nearest_set_bit(fgm, i);
    const int dbg = nearest_set_bit(bgm, i);

    const float fn = (dfg >= W) ? INF_SQ : (float)(dfg * dfg);
    const float fp = (dbg >= W) ? INF_SQ : (float)(dbg * dbg);
    g_row[row * W + i] = make_float2(fn, fp);
}

// -------- Column pass: one thread per output pixel, counted loop. --------
// D[i] = min_k g[k] + (i-k)^2. The o = 0 candidate bounds the result:
// best <= bmax = max(own.x, own.y), so no offset with o^2 >= bmax can win.
// R = (int)sqrtf(bmax) + 1: any o > R has o^2 > bmax >= best, so it cannot
// win (exact; bmax is an exact fp32 integer or INF). Clamped to H-1
// (degenerate INF rows -> full exact scan). Trip count is load-independent,
// so loads stream with full MLP instead of one L2-latency round per
// iteration. Edge clamp is exact: the clamped candidate g[0] + o^2 (o > i)
// >= g[0] + i^2 folded at o == i.
#define CP_THREADS 256
__global__ void __launch_bounds__(CP_THREADS) col_pass(float* __restrict__ out) {
    const int idx = blockIdx.x * CP_THREADS + threadIdx.x;  // 0 .. BATCH*H*W-1
    const int c   = idx & (W - 1);
    const int t   = idx >> 9;            // W == 512
    const int i   = t & (H - 1);
    const int b   = t >> 9;              // H == 512

    const float2* __restrict__ g = g_row + b * H * W;

    const float2 own = g[i * W + c];
    float bn = own.x;
    float bp = own.y;

    const float bmax = fmaxf(bn, bp);
    int R = (int)sqrtf(bmax) + 1;
    if (R > H - 1) R = H - 1;

    #pragma unroll 4
    for (int o = 1; o <= R; ++o) {
        const float o2 = (float)(o * o);
        int ku = i - o; ku = (ku < 0) ? 0 : ku;
        int kd = i + o; kd = (kd >= H) ? H - 1 : kd;
        const float2 u = g[ku * W + c];
        const float2 d = g[kd * W + c];
        bn = fminf(bn, fminf(u.x, d.x) + o2);
        bp = fminf(bp, fminf(u.y, d.y) + o2);
    }

    out[idx] = sqrtf(bn) - sqrtf(bp);
}

extern "C" void kernel_launch(void* const* d_in, const int* in_sizes, int n_in,
                              void* d_out, int out_size) {
    const float* mask = (const float*)d_in[0];
    float* out = (float*)d_out;

    row_pass<<<BATCH * H, W>>>(mask);
    col_pass<<<(BATCH * H * W) / CP_THREADS, CP_THREADS>>>(out);
}

// round 13
// speedup vs baseline: 1.1204x; 1.1204x over previous
#include <cuda_runtime.h>
#include <cuda_bf16.h>
#include <cstdint>

#define BATCH 2
#define H 512
#define W 512
#define NWORDS (W / 32)          // 16
#define INF_SQ 1e12f

// Row-pass output, packed: .x = dist^2 to nearest fg (mask==1) in the row,
//                          .y = dist^2 to nearest bg (mask==0) in the row.
__device__ float2 g_row[BATCH * H * W];

// Nearest set bit to position i in a 512-bit mask (16 words). Returns a huge
// value if no bit is set. Typical path: no word-escape loops taken.
__device__ __forceinline__ int nearest_set_bit(const uint32_t* __restrict__ m, int i) {
    const int wi = i >> 5, bi = i & 31;
    int dL = 1 << 20, dR = 1 << 20;

    const uint32_t below = m[wi] & (0xffffffffu >> (31 - bi));   // bits 0..bi
    if (below) {
        dL = bi - (31 - __clz(below));
    } else {
        for (int j = wi - 1; j >= 0; --j)
            if (m[j]) { dL = i - (j * 32 + 31 - __clz(m[j])); break; }
    }

    const uint32_t above = m[wi] & (0xffffffffu << bi);          // bits bi..31
    if (above) {
        dR = (__ffs(above) - 1) - bi;
    } else {
        for (int j = wi + 1; j < NWORDS; ++j)
            if (m[j]) { dR = j * 32 + (__ffs(m[j]) - 1) - i; break; }
    }

    return min(dL, dR);
}

// -------- Row pass: one block per row; ballot bitmask + O(1) bit search. ----
__global__ void __launch_bounds__(W) row_pass(const float* __restrict__ mask) {
    __shared__ uint32_t fgm[NWORDS];
    __shared__ uint32_t bgm[NWORDS];

    const int row = blockIdx.x;          // 0 .. BATCH*H-1
    const int i   = threadIdx.x;

    const bool isFg = (mask[row * W + i] == 1.0f);
    const uint32_t wm = __ballot_sync(0xffffffffu, isFg);
    if ((i & 31) == 0) {
        fgm[i >> 5] = wm;
        bgm[i >> 5] = ~wm;               // W==512 exactly fills 16 words
    }
    __syncthreads();

    const int dfg = nearest_set_bit(fgm, i);
    const int dbg = nearest_set_bit(bgm, i);

    const float fn = (dfg >= W) ? INF_SQ : (float)(dfg * dfg);
    const float fp = (dbg >= W) ? INF_SQ : (float)(dbg * dbg);
    g_row[row * W + i] = make_float2(fn, fp);
}

// -------- Column pass: prologue (o=1..4, streamed) + early-exit tail. ------
// D[i] = min_k g[k] + (i-k)^2. Prologue folds offsets 1..4 unconditionally:
// genuine candidates, so fminf is exact, and the 8 loads are independent ->
// full MLP, one latency round. Tail from o=5 uses the fully-shrunk running
// bound: continue only if 25 < max(bn, bp) (vanishingly rare for this input;
// degenerate rows still get the exact full scan). Edge clamp is exact: the
// clamped candidate g[0] + o^2 (o > i) >= g[0] + i^2 folded at o == i.
#define CP_THREADS 256
#define PROLOG 4
__global__ void __launch_bounds__(CP_THREADS) col_pass(float* __restrict__ out) {
    const int idx = blockIdx.x * CP_THREADS + threadIdx.x;  // 0 .. BATCH*H*W-1
    const int c   = idx & (W - 1);
    const int t   = idx >> 9;            // W == 512
    const int i   = t & (H - 1);
    const int b   = t >> 9;              // H == 512

    const float2* __restrict__ g = g_row + b * H * W;

    const float2 own = g[i * W + c];
    float bn = own.x;
    float bp = own.y;

    // Streamed prologue: all loads independent of bn/bp.
    float2 u[PROLOG], d[PROLOG];
    #pragma unroll
    for (int o = 1; o <= PROLOG; ++o) {
        int ku = i - o; ku = (ku < 0) ? 0 : ku;
        int kd = i + o; kd = (kd >= H) ? H - 1 : kd;
        u[o - 1] = g[ku * W + c];
        d[o - 1] = g[kd * W + c];
    }
    #pragma unroll
    for (int o = 1; o <= PROLOG; ++o) {
        const float o2 = (float)(o * o);
        bn = fminf(bn, fminf(u[o - 1].x, d[o - 1].x) + o2);
        bp = fminf(bp, fminf(u[o - 1].y, d[o - 1].y) + o2);
    }

    // Rare tail: exact early-exit search from o = PROLOG + 1.
    #pragma unroll 1
    for (int o = PROLOG + 1; o < H; ++o) {
        const float o2 = (float)(o * o);
        if (o2 >= bn && o2 >= bp) break;
        int ku = i - o; ku = (ku < 0) ? 0 : ku;
        int kd = i + o; kd = (kd >= H) ? H - 1 : kd;
        const float2 uu = g[ku * W + c];
        const float2 dd = g[kd * W + c];
        bn = fminf(bn, fminf(uu.x, dd.x) + o2);
        bp = fminf(bp, fminf(uu.y, dd.y) + o2);
    }

    out[idx] = sqrtf(bn) - sqrtf(bp);
}

extern "C" void kernel_launch(void* const* d_in, const int* in_sizes, int n_in,
                              void* d_out, int out_size) {
    const float* mask = (const float*)d_in[0];
    float* out = (float*)d_out;

    row_pass<<<BATCH * H, W>>>(mask);
    col_pass<<<(BATCH * H * W) / CP_THREADS, CP_THREADS>>>(out);
}

// round 17
// speedup vs baseline: 1.1662x; 1.0408x over previous
#include <cuda_runtime.h>
#include <cuda_bf16.h>
#include <cstdint>

#define BATCH 2
#define H 512
#define W 512
#define NWORDS (W / 32)          // 16
#define INF_SQ 1e12f

// Row-pass output, packed: .x = dist^2 to nearest fg (mask==1) in the row,
//                          .y = dist^2 to nearest bg (mask==0) in the row.
__device__ float2 g_row[BATCH * H * W];

// Nearest set bit to position i in a 512-bit mask (16 words). Returns a huge
// value if no bit is set. Typical path: no word-escape loops taken.
__device__ __forceinline__ int nearest_set_bit(const uint32_t* __restrict__ m, int i) {
    const int wi = i >> 5, bi = i & 31;
    int dL = 1 << 20, dR = 1 << 20;

    const uint32_t below = m[wi] & (0xffffffffu >> (31 - bi));   // bits 0..bi
    if (below) {
        dL = bi - (31 - __clz(below));
    } else {
        for (int j = wi - 1; j >= 0; --j)
            if (m[j]) { dL = i - (j * 32 + 31 - __clz(m[j])); break; }
    }

    const uint32_t above = m[wi] & (0xffffffffu << bi);          // bits bi..31
    if (above) {
        dR = (__ffs(above) - 1) - bi;
    } else {
        for (int j = wi + 1; j < NWORDS; ++j)
            if (m[j]) { dR = j * 32 + (__ffs(m[j]) - 1) - i; break; }
    }

    return min(dL, dR);
}

// -------- Row pass: one block per row; ballot bitmask + O(1) bit search. ----
__global__ void __launch_bounds__(W) row_pass(const float* __restrict__ mask) {
    __shared__ uint32_t fgm[NWORDS];
    __shared__ uint32_t bgm[NWORDS];

    const int row = blockIdx.x;          // 0 .. BATCH*H-1
    const int i   = threadIdx.x;

    const bool isFg = (mask[row * W + i] == 1.0f);
    const uint32_t wm = __ballot_sync(0xffffffffu, isFg);
    if ((i & 31) == 0) {
        fgm[i >> 5] = wm;
        bgm[i >> 5] = ~wm;               // W==512 exactly fills 16 words
    }
    __syncthreads();

    const int dfg = nearest_set_bit(fgm, i);
    const int dbg = nearest_set_bit(bgm, i);

    const float fn = (dfg >= W) ? INF_SQ : (float)(dfg * dfg);
    const float fp = (dbg >= W) ? INF_SQ : (float)(dbg * dbg);
    g_row[row * W + i] = make_float2(fn, fp);
}

// -------- Column pass: PIX rows per thread, shared candidate window. -------
// D[i] = min_k g[k] + (i-k)^2. One thread computes PIX=4 consecutive rows of
// one column. Window rows i0-4 .. i0+7 are loaded once (12 independent,
// coalesced float2 loads); each pixel folds its 9 candidates (offsets -4..4)
// from registers. Folding genuine candidates with fminf is exact. Edge clamp
// is exact: for i <= 4 the true boundary row 0 appears at o == i, so any
// clamped duplicate g[0] + o^2 (o > i) cannot win. Rare tail from o = 5 uses
// the fully shrunk running bound (entered only if max(bn,bp) > 25; degenerate
// rows still get the exact full scan).
#define CP_THREADS 256
#define PIX 4
__global__ void __launch_bounds__(CP_THREADS) col_pass(float* __restrict__ out) {
    const int tid = blockIdx.x * CP_THREADS + threadIdx.x;  // 0 .. BATCH*H*W/PIX-1
    const int c   = tid & (W - 1);
    const int t   = tid >> 9;            // W == 512
    const int i0  = (t & (H / PIX - 1)) * PIX;   // 0, 4, 8, ..., 508
    const int b   = t >> 7;              // H/PIX == 128

    const float2* __restrict__ g = g_row + b * H * W;

    // Load the shared candidate window: rows i0-4 .. i0+7 (clamped).
    float2 v[PIX + 8];
    #pragma unroll
    for (int j = 0; j < PIX + 8; ++j) {
        int r = i0 - 4 + j;
        r = (r < 0) ? 0 : ((r >= H) ? H - 1 : r);
        v[j] = g[r * W + c];
    }

    #pragma unroll
    for (int p = 0; p < PIX; ++p) {
        const int i = i0 + p;
        float bn = v[p + 4].x;
        float bp = v[p + 4].y;

        #pragma unroll
        for (int q = 1; q <= 4; ++q) {
            const float o2 = (float)(q * q);
            bn = fminf(bn, fminf(v[p + 4 - q].x, v[p + 4 + q].x) + o2);
            bp = fminf(bp, fminf(v[p + 4 - q].y, v[p + 4 + q].y) + o2);
        }

        // Rare exact tail.
        #pragma unroll 1
        for (int o = 5; o < H; ++o) {
            const float o2 = (float)(o * o);
            if (o2 >= bn && o2 >= bp) break;
            int ku = i - o; ku = (ku < 0) ? 0 : ku;
            int kd = i + o; kd = (kd >= H) ? H - 1 : kd;
            const float2 uu = g[ku * W + c];
            const float2 dd = g[kd * W + c];
            bn = fminf(bn, fminf(uu.x, dd.x) + o2);
            bp = fminf(bp, fminf(uu.y, dd.y) + o2);
        }

        out[(b * H + i) * W + c] = sqrtf(bn) - sqrtf(bp);
    }
}

extern "C" void kernel_launch(void* const* d_in, const int* in_sizes, int n_in,
                              void* d_out, int out_size) {
    const float* mask = (const float*)d_in[0];
    float* out = (float*)d_out;

    row_pass<<<BATCH * H, W>>>(mask);
    col_pass<<<(BATCH * H * W / PIX) / CP_THREADS, CP_THREADS>>>(out);
}